// round 9
// baseline (speedup 1.0000x reference)
#include <cuda_runtime.h>

// GRUExtractor: 2-layer GRU, B=4096, T=256, I=16, H=40, fp32.
// R9: pair-split work decomposition to kill register spills.
//  - warps 0-7  (256 thr): L0. lane pair (2k,2k+1) owns unit p=(r>>1): even/odd
//    half-split of Whh0 row (10 u64 each) + Wih0 row (4 u64 each). 14 weight regs.
//  - warps 8-15 (256 thr): L1. even lane = Wih1 row (dot over h0), odd lane =
//    Whh1 row (dot over h1). 20 weight regs.
//  - partials combined via __shfl_xor_sync(.,1); dummy pair-slots (p>=120)
//    clamped so warps stay converged (full-mask shuffles).
//  - x(s+1) prefetched into registers by threads r<112, STS'd after Phase A.
//  - 28 batch rows per CTA, grid 148, __syncthreads barriers.

#define HSZ 40
#define ISZ 16
#define TSZ 256
#define NB  4096
#define NR  28
#define CTA_T 512

typedef unsigned long long u64;
typedef ulonglong2 u64x2;

__device__ __forceinline__ void upk2(u64 d, float& a, float& b) {
    asm("mov.b64 {%0,%1},%2;" : "=f"(a), "=f"(b) : "l"(d));
}
__device__ __forceinline__ u64 ffma2(u64 a, u64 b, u64 c) {
    u64 d; asm("fma.rn.f32x2 %0,%1,%2,%3;" : "=l"(d) : "l"(a), "l"(b), "l"(c)); return d;
}
__device__ __forceinline__ float hsum2(u64 d) { float a, b; upk2(d, a, b); return a + b; }

__device__ __forceinline__ float sigm(float x) {
    return __fdividef(1.0f, 1.0f + __expf(-x));
}
__device__ __forceinline__ float tanh_f(float x) {
    return __fdividef(2.0f, 1.0f + __expf(-2.0f * x)) - 1.0f;
}

__global__ void __launch_bounds__(CTA_T, 1) gru_fused_kernel(
    const float* __restrict__ x,     // (B, T, I)
    const float* __restrict__ Wih0,  // (120, 16)
    const float* __restrict__ Whh0,  // (120, 40)
    const float* __restrict__ bih0,  // (120)
    const float* __restrict__ bhh0,  // (120)
    const float* __restrict__ Wih1,  // (120, 40)
    const float* __restrict__ Whh1,  // (120, 40)
    const float* __restrict__ bih1,  // (120)
    const float* __restrict__ bhh1,  // (120)
    float* __restrict__ out)         // (B, 40)
{
    __shared__ __align__(16) float h0s[NR][HSZ];
    __shared__ __align__(16) float h1s[NR][HSZ];
    __shared__ __align__(16) float ras[2][NR][HSZ];
    __shared__ __align__(16) float zas[2][NR][HSZ];
    __shared__ __align__(16) float nxs[2][NR][HSZ];
    __shared__ __align__(16) float nhs[2][NR][HSZ];
    __shared__ __align__(16) float xbs[2][NR][ISZ];

    const int r = threadIdx.x;
    const int base = blockIdx.x * NR;

    const bool inL0 = (r < 256);
    const int  praw = (inL0 ? r : (r - 256)) >> 1;
    const bool real = (praw < 120);
    const int  p    = real ? praw : 119;
    const int  half = r & 1;
    const int  g    = p / 40;
    const int  j    = p - g * 40;
    const int  wr   = g * 40 + j;

    // ---- register-cached weights ----
    u64 wA[20];          // L0: 10 used; L1: 20 used
    u64 wX[4];           // L0 only
    float bx = 0.0f, bh = 0.0f;

    if (inL0) {
        const u64x2* ph = (const u64x2*)(Whh0 + wr * HSZ + half * 20);
        #pragma unroll
        for (int q = 0; q < 5; q++) { u64x2 v = ph[q]; wA[2*q] = v.x; wA[2*q+1] = v.y; }
        const u64x2* px = (const u64x2*)(Wih0 + wr * ISZ + half * 8);
        #pragma unroll
        for (int q = 0; q < 2; q++) { u64x2 v = px[q]; wX[2*q] = v.x; wX[2*q+1] = v.y; }
        if (g < 2) { bx = bih0[wr] + bhh0[wr]; }
        else       { bx = bih0[wr]; bh = bhh0[wr]; }
    } else {
        const float* Wsel = half ? (Whh1 + wr * HSZ) : (Wih1 + wr * HSZ);
        const u64x2* pw = (const u64x2*)Wsel;
        #pragma unroll
        for (int q = 0; q < 10; q++) { u64x2 v = pw[q]; wA[2*q] = v.x; wA[2*q+1] = v.y; }
        if (g < 2) { bx = bih1[wr] + bhh1[wr]; }
        else       { bx = half ? bhh1[wr] : bih1[wr]; }
    }

    // ---- init: zero h, stage x(t=0) ----
    for (int e = r; e < NR * HSZ; e += CTA_T) {
        h0s[e / HSZ][e % HSZ] = 0.0f;
        h1s[e / HSZ][e % HSZ] = 0.0f;
    }
    if (r < NR * 4) {
        int row = r >> 2, c = r & 3;
        int gr = base + row; if (gr > NB - 1) gr = NB - 1;
        ((float4*)xbs[0][row])[c] = ((const float4*)x)[(gr * TSZ + 0) * 4 + c];
    }
    __syncthreads();

    // ---- supersteps: L0 computes t=s, L1 computes t=s-1 ----
    for (int s = 0; s <= TSZ; ++s) {
        // register prefetch of x(s+1) (threads 0..111)
        float4 xv;
        const int s1 = s + 1;
        const bool do_pf = (r < NR * 4) && (s1 < TSZ);
        if (do_pf) {
            int row = r >> 2, c = r & 3;
            int gr = base + row; if (gr > NB - 1) gr = NB - 1;
            xv = ((const float4*)x)[(gr * TSZ + s1) * 4 + c];
        }

        // ===== PHASE A =====
        if (inL0) {
            if (s < TSZ) {
                #pragma unroll 7
                for (int row = 0; row < NR; ++row) {
                    const u64x2* hp = (const u64x2*)(&h0s[row][half * 20]);
                    u64 a0 = 0ull, a1 = 0ull;
                    #pragma unroll
                    for (int q = 0; q < 5; q++) {
                        u64x2 v = hp[q];
                        a0 = ffma2(wA[2*q],   v.x, a0);
                        a1 = ffma2(wA[2*q+1], v.y, a1);
                    }
                    const u64x2* xp = (const u64x2*)(&xbs[s & 1][row][half * 8]);
                    u64 b0 = 0ull;
                    #pragma unroll
                    for (int q = 0; q < 2; q++) {
                        u64x2 v = xp[q];
                        b0 = ffma2(wX[2*q],   v.x, b0);
                        b0 = ffma2(wX[2*q+1], v.y, b0);
                    }
                    float hpart = hsum2(a0) + hsum2(a1);
                    float xpart = hsum2(b0);
                    if (g < 2) {
                        float tp = hpart + xpart;
                        float full = tp + __shfl_xor_sync(0xFFFFFFFFu, tp, 1);
                        if (half == 0 && real) {
                            float act = sigm(full + bx);
                            if (g == 0) ras[0][row][j] = act;
                            else        zas[0][row][j] = act;
                        }
                    } else {
                        float hf = hpart + __shfl_xor_sync(0xFFFFFFFFu, hpart, 1);
                        float xf = xpart + __shfl_xor_sync(0xFFFFFFFFu, xpart, 1);
                        if (half == 0 && real) {
                            nxs[0][row][j] = xf + bx;
                            nhs[0][row][j] = hf + bh;
                        }
                    }
                }
            }
        } else {
            if (s >= 1) {
                const float (*hsrc)[HSZ] = half ? h1s : h0s;
                #pragma unroll 4
                for (int row = 0; row < NR; ++row) {
                    const u64x2* hp = (const u64x2*)hsrc[row];
                    u64 a0 = 0ull, a1 = 0ull, a2 = 0ull, a3 = 0ull;
                    #pragma unroll
                    for (int q = 0; q < 5; q++) {
                        u64x2 v0 = hp[2*q], v1 = hp[2*q+1];
                        a0 = ffma2(wA[4*q],   v0.x, a0);
                        a1 = ffma2(wA[4*q+1], v0.y, a1);
                        a2 = ffma2(wA[4*q+2], v1.x, a2);
                        a3 = ffma2(wA[4*q+3], v1.y, a3);
                    }
                    float part = (hsum2(a0) + hsum2(a1)) + (hsum2(a2) + hsum2(a3));
                    if (g < 2) {
                        float full = part + __shfl_xor_sync(0xFFFFFFFFu, part, 1);
                        if (half == 0 && real) {
                            float act = sigm(full + bx);
                            if (g == 0) ras[1][row][j] = act;
                            else        zas[1][row][j] = act;
                        }
                    } else {
                        if (real) {
                            if (half == 0) nxs[1][row][j] = part + bx;
                            else           nhs[1][row][j] = part + bx;
                        }
                    }
                }
            }
        }

        // commit prefetched x(s+1) to the other parity buffer
        if (do_pf) {
            int row = r >> 2, c = r & 3;
            ((float4*)xbs[s1 & 1][row])[c] = xv;
        }
        __syncthreads();

        // ===== PHASE B: h update over all 512 threads (2240 tasks) =====
        #pragma unroll
        for (int k = 0; k < 5; k++) {
            int task = r + CTA_T * k;
            if (task < 2 * NR * HSZ) {
                int lay = task / (NR * HSZ);
                int rem = task - lay * (NR * HSZ);
                int row = rem / HSZ;
                int jj  = rem - row * HSZ;
                bool ok = lay == 0 ? (s < TSZ) : (s >= 1);
                if (ok) {
                    float rr = ras[lay][row][jj];
                    float zz = zas[lay][row][jj];
                    float xn = nxs[lay][row][jj];
                    float hn = nhs[lay][row][jj];
                    float n  = tanh_f(fmaf(rr, hn, xn));
                    float* hp = lay == 0 ? &h0s[row][jj] : &h1s[row][jj];
                    float ho = *hp;
                    *hp = fmaf(zz, ho - n, n);
                }
            }
        }
        __syncthreads();
    }

    // ---- write final layer-1 hidden state (clamped rows dup, benign) ----
    for (int e = r; e < NR * HSZ; e += CTA_T) {
        int row = e / HSZ, jj = e % HSZ;
        int gr = base + row; if (gr > NB - 1) gr = NB - 1;
        out[gr * HSZ + jj] = h1s[row][jj];
    }
}

extern "C" void kernel_launch(void* const* d_in, const int* in_sizes, int n_in,
                              void* d_out, int out_size) {
    const float* x    = (const float*)d_in[0];
    const float* Wih0 = (const float*)d_in[1];
    const float* Whh0 = (const float*)d_in[2];
    const float* bih0 = (const float*)d_in[3];
    const float* bhh0 = (const float*)d_in[4];
    const float* Wih1 = (const float*)d_in[5];
    const float* Whh1 = (const float*)d_in[6];
    const float* bih1 = (const float*)d_in[7];
    const float* bhh1 = (const float*)d_in[8];
    float* out = (float*)d_out;

    gru_fused_kernel<<<148, CTA_T>>>(x, Wih0, Whh0, bih0, bhh0,
                                     Wih1, Whh1, bih1, bhh1, out);
}

// round 11
// speedup vs baseline: 2.2424x; 2.2424x over previous
#include <cuda_runtime.h>

// GRUExtractor: 2-layer GRU, B=4096, T=256, I=16, H=40, fp32.
// R11 = R10 with the Wih0 truncation bug fixed (wX[8], full 16-element x dot).
//  - per slot (384 thr): 120 L0 threads (own (g,j), full rows),
//    240 L1 threads (matrix-split: even lane Wih1 row . h0, odd lane Whh1 row . h1,
//    partials -> smem pI/pH; combined in Phase B — NO shuffles),
//    24 x-prefetch threads.
//  - Phase B (all 384 slot threads): L0 tanh+update; L1 sigm/sigm/tanh+update.
//  - dynamic smem (57 KB), per-slot named barriers, 768-thread CTA.

#define HSZ 40
#define ISZ 16
#define TSZ 256
#define NB  4096
#define NR  14
#define SLOT_T 384
#define CTA_T  768

typedef unsigned long long u64;
typedef ulonglong2 u64x2;

__device__ __forceinline__ void upk2(u64 d, float& a, float& b) {
    asm("mov.b64 {%0,%1},%2;" : "=f"(a), "=f"(b) : "l"(d));
}
__device__ __forceinline__ u64 ffma2(u64 a, u64 b, u64 c) {
    u64 d; asm("fma.rn.f32x2 %0,%1,%2,%3;" : "=l"(d) : "l"(a), "l"(b), "l"(c)); return d;
}
__device__ __forceinline__ float hsum2(u64 d) { float a, b; upk2(d, a, b); return a + b; }

__device__ __forceinline__ float sigm(float x) {
    return __fdividef(1.0f, 1.0f + __expf(-x));
}
__device__ __forceinline__ float tanh_f(float x) {
    return __fdividef(2.0f, 1.0f + __expf(-2.0f * x)) - 1.0f;
}

__device__ __forceinline__ void slot_bar(int slot) {
    asm volatile("bar.sync %0, %1;" :: "r"(slot + 1), "r"(SLOT_T) : "memory");
}

struct SlotMem {
    float h0[NR][HSZ];
    float h1[NR][HSZ];
    float Ra[NR][HSZ];          // L0 r gate (activated)
    float Za[NR][HSZ];          // L0 z gate (activated)
    float Nx[NR][HSZ];          // L0 n-gate x part (+bih)
    float Nh[NR][HSZ];          // L0 n-gate h part (+bhh)
    float pI[NR][3 * HSZ];      // L1 input-side partials (+bih1)
    float pH[NR][3 * HSZ];      // L1 hidden-side partials (+bhh1)
    float xb[2][NR][ISZ];       // x double buffer
};

__global__ void __launch_bounds__(CTA_T, 1) gru_fused_kernel(
    const float* __restrict__ x,     // (B, T, I)
    const float* __restrict__ Wih0,  // (120, 16)
    const float* __restrict__ Whh0,  // (120, 40)
    const float* __restrict__ bih0,  // (120)
    const float* __restrict__ bhh0,  // (120)
    const float* __restrict__ Wih1,  // (120, 40)
    const float* __restrict__ Whh1,  // (120, 40)
    const float* __restrict__ bih1,  // (120)
    const float* __restrict__ bhh1,  // (120)
    float* __restrict__ out)         // (B, 40)
{
    extern __shared__ __align__(16) char smem_raw[];
    SlotMem* sm = (SlotMem*)smem_raw;

    const int tid  = threadIdx.x;
    const int slot = tid / SLOT_T;
    const int r    = tid - slot * SLOT_T;
    SlotMem& S = sm[slot];

    const int slot_id = blockIdx.x * 2 + slot;
    const int base = slot_id * NR;

    // ---- thread roles ----
    const bool isL0 = (r < 120);
    const bool isL1 = (r >= 128 && r < 368);
    int pfid = -1;
    if (r >= 120 && r < 128) pfid = r - 120;          // 0..7
    else if (r >= 368)       pfid = 8 + (r - 368);    // 8..23

    const int p    = isL1 ? ((r - 128) >> 1) : r;     // unit id 0..119
    const int half = r & 1;                           // L1: 0=ih, 1=hh
    const int g    = (p < 120) ? p / 40 : 0;
    const int j    = (p < 120) ? (p - g * 40) : 0;
    const int wr   = g * 40 + j;

    // ---- register-cached weights ----
    u64 wA[20], wX[8];
    float bx = 0.0f, bh = 0.0f;

    if (isL0) {
        const u64x2* ph = (const u64x2*)(Whh0 + wr * HSZ);
        #pragma unroll
        for (int q = 0; q < 10; q++) { u64x2 v = ph[q]; wA[2*q] = v.x; wA[2*q+1] = v.y; }
        const u64x2* px = (const u64x2*)(Wih0 + wr * ISZ);
        #pragma unroll
        for (int q = 0; q < 4; q++) { u64x2 v = px[q]; wX[2*q] = v.x; wX[2*q+1] = v.y; }
        if (g < 2) { bx = bih0[wr] + bhh0[wr]; bh = 0.0f; }
        else       { bx = bih0[wr];            bh = bhh0[wr]; }
    } else if (isL1) {
        const float* Wsel = half ? (Whh1 + wr * HSZ) : (Wih1 + wr * HSZ);
        const u64x2* pw = (const u64x2*)Wsel;
        #pragma unroll
        for (int q = 0; q < 10; q++) { u64x2 v = pw[q]; wA[2*q] = v.x; wA[2*q+1] = v.y; }
        bx = half ? bhh1[wr] : bih1[wr];
    }

    // ---- init: zero h, stage x(t=0) ----
    for (int e = r; e < NR * HSZ; e += SLOT_T) {
        S.h0[e / HSZ][e % HSZ] = 0.0f;
        S.h1[e / HSZ][e % HSZ] = 0.0f;
    }
    if (pfid >= 0) {
        #pragma unroll
        for (int k = 0; k < 3; k++) {
            int idx = pfid + 24 * k;
            if (idx < NR * 4) {
                int row = idx >> 2, c = idx & 3;
                int gr = base + row; if (gr > NB - 1) gr = NB - 1;
                ((float4*)S.xb[0][row])[c] = ((const float4*)x)[(gr * TSZ) * 4 + c];
            }
        }
    }
    __syncthreads();

    // ---- supersteps: L0 computes t=s, L1 computes t=s-1 ----
    for (int s = 0; s <= TSZ; ++s) {
        // register prefetch of x(s+1)
        float4 xv0, xv1, xv2;
        const int s1 = s + 1;
        const bool do_pf = (pfid >= 0) && (s1 < TSZ);
        if (do_pf) {
            #pragma unroll
            for (int k = 0; k < 3; k++) {
                int idx = pfid + 24 * k;
                if (idx < NR * 4) {
                    int row = idx >> 2, c = idx & 3;
                    int gr = base + row; if (gr > NB - 1) gr = NB - 1;
                    float4 v = ((const float4*)x)[(gr * TSZ + s1) * 4 + c];
                    if (k == 0) xv0 = v; else if (k == 1) xv1 = v; else xv2 = v;
                }
            }
        }

        // ===== PHASE A =====
        if (isL0) {
            if (s < TSZ) {
                #pragma unroll 7
                for (int row = 0; row < NR; ++row) {
                    const u64x2* hp = (const u64x2*)S.h0[row];
                    u64 a0 = 0ull, a1 = 0ull;
                    #pragma unroll
                    for (int q = 0; q < 5; q++) {
                        u64x2 v0 = hp[2*q], v1 = hp[2*q+1];
                        a0 = ffma2(wA[4*q],   v0.x, a0);
                        a1 = ffma2(wA[4*q+1], v0.y, a1);
                        a0 = ffma2(wA[4*q+2], v1.x, a0);
                        a1 = ffma2(wA[4*q+3], v1.y, a1);
                    }
                    const u64x2* xp = (const u64x2*)S.xb[s & 1][row];
                    u64 b0 = 0ull, b1 = 0ull;
                    #pragma unroll
                    for (int q = 0; q < 2; q++) {
                        u64x2 v0 = xp[2*q], v1 = xp[2*q+1];
                        b0 = ffma2(wX[4*q],   v0.x, b0);
                        b1 = ffma2(wX[4*q+1], v0.y, b1);
                        b0 = ffma2(wX[4*q+2], v1.x, b0);
                        b1 = ffma2(wX[4*q+3], v1.y, b1);
                    }
                    float sH = hsum2(a0) + hsum2(a1);
                    float sX = hsum2(b0) + hsum2(b1);
                    if (g == 0)      S.Ra[row][j] = sigm(sX + sH + bx);
                    else if (g == 1) S.Za[row][j] = sigm(sX + sH + bx);
                    else { S.Nx[row][j] = sX + bx; S.Nh[row][j] = sH + bh; }
                }
            }
        } else if (isL1) {
            if (s >= 1) {
                const float (*hsrc)[HSZ] = half ? S.h1 : S.h0;
                float* pdst = half ? &S.pH[0][0] : &S.pI[0][0];
                #pragma unroll 7
                for (int row = 0; row < NR; ++row) {
                    const u64x2* hp = (const u64x2*)hsrc[row];
                    u64 a0 = 0ull, a1 = 0ull, a2 = 0ull, a3 = 0ull;
                    #pragma unroll
                    for (int q = 0; q < 5; q++) {
                        u64x2 v0 = hp[2*q], v1 = hp[2*q+1];
                        a0 = ffma2(wA[4*q],   v0.x, a0);
                        a1 = ffma2(wA[4*q+1], v0.y, a1);
                        a2 = ffma2(wA[4*q+2], v1.x, a2);
                        a3 = ffma2(wA[4*q+3], v1.y, a3);
                    }
                    float part = (hsum2(a0) + hsum2(a1)) + (hsum2(a2) + hsum2(a3));
                    pdst[row * (3 * HSZ) + wr] = part + bx;
                }
            }
        }

        // commit prefetched x(s+1)
        if (do_pf) {
            #pragma unroll
            for (int k = 0; k < 3; k++) {
                int idx = pfid + 24 * k;
                if (idx < NR * 4) {
                    int row = idx >> 2, c = idx & 3;
                    float4 v = (k == 0) ? xv0 : (k == 1) ? xv1 : xv2;
                    ((float4*)S.xb[s1 & 1][row])[c] = v;
                }
            }
        }
        slot_bar(slot);

        // ===== PHASE B: updates over all 384 slot threads (1120 tasks) =====
        #pragma unroll
        for (int k = 0; k < 3; k++) {
            int task = r + SLOT_T * k;
            if (task < 2 * NR * HSZ) {
                if (task < NR * HSZ) {
                    // layer 0
                    if (s < TSZ) {
                        int row = task / HSZ, jj = task - (task / HSZ) * HSZ;
                        float rr = S.Ra[row][jj];
                        float zz = S.Za[row][jj];
                        float n  = tanh_f(fmaf(rr, S.Nh[row][jj], S.Nx[row][jj]));
                        float ho = S.h0[row][jj];
                        S.h0[row][jj] = fmaf(zz, ho - n, n);
                    }
                } else {
                    // layer 1
                    if (s >= 1) {
                        int t2  = task - NR * HSZ;
                        int row = t2 / HSZ, jj = t2 - (t2 / HSZ) * HSZ;
                        float rr = sigm(S.pI[row][jj]        + S.pH[row][jj]);
                        float zz = sigm(S.pI[row][HSZ + jj]  + S.pH[row][HSZ + jj]);
                        float n  = tanh_f(fmaf(rr, S.pH[row][2 * HSZ + jj],
                                                    S.pI[row][2 * HSZ + jj]));
                        float ho = S.h1[row][jj];
                        S.h1[row][jj] = fmaf(zz, ho - n, n);
                    }
                }
            }
        }
        slot_bar(slot);
    }

    // ---- write final layer-1 hidden state (clamped rows dup, benign) ----
    for (int e = r; e < NR * HSZ; e += SLOT_T) {
        int row = e / HSZ, jj = e % HSZ;
        int gr = base + row; if (gr > NB - 1) gr = NB - 1;
        out[gr * HSZ + jj] = S.h1[row][jj];
    }
}

extern "C" void kernel_launch(void* const* d_in, const int* in_sizes, int n_in,
                              void* d_out, int out_size) {
    const float* x    = (const float*)d_in[0];
    const float* Wih0 = (const float*)d_in[1];
    const float* Whh0 = (const float*)d_in[2];
    const float* bih0 = (const float*)d_in[3];
    const float* bhh0 = (const float*)d_in[4];
    const float* Wih1 = (const float*)d_in[5];
    const float* Whh1 = (const float*)d_in[6];
    const float* bih1 = (const float*)d_in[7];
    const float* bhh1 = (const float*)d_in[8];
    float* out = (float*)d_out;

    const int smem_bytes = 2 * (int)sizeof(SlotMem);
    cudaFuncSetAttribute(gru_fused_kernel,
                         cudaFuncAttributeMaxDynamicSharedMemorySize, smem_bytes);
    gru_fused_kernel<<<148, CTA_T, smem_bytes>>>(x, Wih0, Whh0, bih0, bhh0,
                                                 Wih1, Whh1, bih1, bhh1, out);
}

// round 12
// speedup vs baseline: 2.8148x; 1.2552x over previous
#include <cuda_runtime.h>

// GRUExtractor: 2-layer GRU, B=4096, T=256, I=16, H=40, fp32.
// R12: (a) xg prepass kernel (Wih0.x + bih0 -> 503MB device scratch) removes
//      the x-dot from the recurrent loop; (b) U=2 gate-rows per thread with
//      warp-uniform k-half split -> each broadcast LDS.128 of h feeds 4 ffma2
//      (was 2); partials combined in Phase B via smem (no shuffles).
// CTA 768 = 2 slots x 384 (128 L0 threads + 256 L1 threads each), NR=14/slot.

#define HSZ 40
#define ISZ 16
#define TSZ 256
#define NB  4096
#define NR  14
#define SLOT_T 384
#define CTA_T  768
#define NGR 120

typedef unsigned long long u64;
typedef ulonglong2 u64x2;

__device__ float g_xg[(size_t)NB * TSZ * NGR];   // xg[b][t][gate_row]

__device__ __forceinline__ void upk2(u64 d, float& a, float& b) {
    asm("mov.b64 {%0,%1},%2;" : "=f"(a), "=f"(b) : "l"(d));
}
__device__ __forceinline__ u64 ffma2(u64 a, u64 b, u64 c) {
    u64 d; asm("fma.rn.f32x2 %0,%1,%2,%3;" : "=l"(d) : "l"(a), "l"(b), "l"(c)); return d;
}
__device__ __forceinline__ float hsum2(u64 d) { float a, b; upk2(d, a, b); return a + b; }

__device__ __forceinline__ float sigm(float x) {
    return __fdividef(1.0f, 1.0f + __expf(-x));
}
__device__ __forceinline__ float tanh_f(float x) {
    return __fdividef(2.0f, 1.0f + __expf(-2.0f * x)) - 1.0f;
}

__device__ __forceinline__ void slot_bar(int slot) {
    asm volatile("bar.sync %0, %1;" :: "r"(slot + 1), "r"(SLOT_T) : "memory");
}

// ---------------- prepass: xg = Wih0 . x + bih0 ----------------
__global__ void __launch_bounds__(128, 8) xg_prepass(
    const float* __restrict__ x, const float* __restrict__ Wih0,
    const float* __restrict__ bih0)
{
    __shared__ __align__(16) float4 xs[TSZ * 4];   // one batch row: 256 t x 16 floats
    const int b = blockIdx.x;
    const int tid = threadIdx.x;
    for (int i = tid; i < TSZ * 4; i += 128)
        xs[i] = ((const float4*)x)[b * (TSZ * 4) + i];
    u64 w[8]; float bias = 0.0f;
    const int gr = tid;
    if (gr < NGR) {
        const u64x2* wp = (const u64x2*)(Wih0 + gr * ISZ);
        #pragma unroll
        for (int q = 0; q < 4; q++) { u64x2 v = wp[q]; w[2*q] = v.x; w[2*q+1] = v.y; }
        bias = bih0[gr];
    }
    __syncthreads();
    if (gr < NGR) {
        float* dst = g_xg + (size_t)b * TSZ * NGR + gr;
        #pragma unroll 4
        for (int t = 0; t < TSZ; t++) {
            const u64x2* xp = (const u64x2*)&xs[t * 4];
            u64 a0 = 0ull, a1 = 0ull;
            #pragma unroll
            for (int q = 0; q < 4; q++) {
                u64x2 v = xp[q];
                a0 = ffma2(w[2*q],   v.x, a0);
                a1 = ffma2(w[2*q+1], v.y, a1);
            }
            dst[t * NGR] = hsum2(a0) + hsum2(a1) + bias;
        }
    }
}

// ---------------- main recurrent kernel ----------------
struct Slot {
    float h0[NR][HSZ];            // 2240 B
    float h1[NR][HSZ];            // 2240 B
    float pA[2][NR][NGR];         // L0 partials [half]      13440 B
    float pB[2][2][NR][NGR];      // L1 partials [mat][half] 26880 B
    float xb[2][NR][NGR];         // xg double buffer        13440 B
};
struct CTAS {
    Slot sl[2];
    float bhh0[NGR], bih1[NGR], bhh1[NGR];
};

__global__ void __launch_bounds__(CTA_T, 1) gru_main(
    const float* __restrict__ Whh0,
    const float* __restrict__ bhh0,
    const float* __restrict__ Wih1,
    const float* __restrict__ Whh1,
    const float* __restrict__ bih1,
    const float* __restrict__ bhh1,
    float* __restrict__ out)
{
    extern __shared__ __align__(16) char smraw[];
    CTAS& C = *(CTAS*)smraw;

    const int tid  = threadIdx.x;
    const int slot = tid / SLOT_T;
    const int r    = tid - slot * SLOT_T;
    Slot& S = C.sl[slot];
    const int base = (blockIdx.x * 2 + slot) * NR;

    // ---- roles: r<128 -> L0 (warp-uniform half); 128..383 -> L1 ----
    const bool isL0 = (r < 128);
    int half, mat = 0, gr0;
    const float* Wsrc;
    if (isL0) {
        half = r >> 6;                       // warps 0-1: half0, warps 2-3: half1
        int m = r & 63; if (m > 59) m = 59;  // dup lanes clamp (benign)
        gr0 = 2 * m;
        Wsrc = Whh0;
    } else {
        int i2 = r - 128;
        half = i2 >> 7;                      // warp-uniform
        mat  = (i2 >> 6) & 1;                // warp-uniform: 0=Wih1(.h0) 1=Whh1(.h1)
        int u = i2 & 63; if (u > 59) u = 59;
        gr0 = 2 * u;
        Wsrc = mat ? Whh1 : Wih1;
    }
    const int hofs = half * 20;

    // ---- register weights: 2 gate-rows x half-k = 20 u64 ----
    u64 w[20];
    {
        const u64x2* p0 = (const u64x2*)(Wsrc + gr0 * HSZ + hofs);
        const u64x2* p1 = (const u64x2*)(Wsrc + (gr0 + 1) * HSZ + hofs);
        #pragma unroll
        for (int q = 0; q < 5; q++) {
            u64x2 v0 = p0[q]; w[2*q]      = v0.x; w[2*q+1]      = v0.y;
            u64x2 v1 = p1[q]; w[10 + 2*q] = v1.x; w[10 + 2*q+1] = v1.y;
        }
    }

    // ---- init: zero h, stage biases, stage xg(t=0) ----
    for (int e = r; e < NR * HSZ; e += SLOT_T) {
        S.h0[e / HSZ][e % HSZ] = 0.0f;
        S.h1[e / HSZ][e % HSZ] = 0.0f;
    }
    if (tid < NGR)               C.bhh0[tid]           = bhh0[tid];
    else if (tid < 2 * NGR)      C.bih1[tid - NGR]     = bih1[tid - NGR];
    else if (tid < 3 * NGR)      C.bhh1[tid - 2 * NGR] = bhh1[tid - 2 * NGR];
    for (int idx = r; idx < NR * 30; idx += SLOT_T) {
        int row = idx / 30, c = idx - row * 30;
        int grow = base + row; if (grow > NB - 1) grow = NB - 1;
        ((float4*)S.xb[0][row])[c] =
            ((const float4*)g_xg)[((size_t)grow * TSZ) * 30 + c];
    }
    __syncthreads();

    // ---- supersteps: L0 computes t=s, L1 computes t=s-1 ----
    for (int s = 0; s <= TSZ; ++s) {
        // register prefetch of xg(s+1)
        float4 pf0, pf1;
        int pi0 = -1, pi1 = -1;
        const int s1 = s + 1;
        if (s1 < TSZ) {
            int idx = r;
            if (idx < NR * 30) {
                int row = idx / 30, c = idx - row * 30;
                int grow = base + row; if (grow > NB - 1) grow = NB - 1;
                pf0 = ((const float4*)g_xg)[((size_t)grow * TSZ + s1) * 30 + c];
                pi0 = idx;
            }
            idx = r + SLOT_T;
            if (idx < NR * 30) {
                int row = idx / 30, c = idx - row * 30;
                int grow = base + row; if (grow > NB - 1) grow = NB - 1;
                pf1 = ((const float4*)g_xg)[((size_t)grow * TSZ + s1) * 30 + c];
                pi1 = idx;
            }
        }

        // ===== PHASE A: partial h-dots (uniform code path) =====
        const bool act = isL0 ? (s < TSZ) : (s >= 1);
        if (act) {
            const float (*hsrc)[HSZ] = (isL0 || mat == 0) ? S.h0 : S.h1;
            float* pout = isL0 ? &S.pA[half][0][0] : &S.pB[mat][half][0][0];
            #pragma unroll 2
            for (int row = 0; row < NR; ++row) {
                const u64x2* hp = (const u64x2*)(&hsrc[row][hofs]);
                u64 a0 = 0ull, a1 = 0ull, b0 = 0ull, b1 = 0ull;
                #pragma unroll
                for (int q = 0; q < 5; q++) {
                    u64x2 v = hp[q];
                    a0 = ffma2(w[2*q],        v.x, a0);
                    a1 = ffma2(w[2*q+1],      v.y, a1);
                    b0 = ffma2(w[10 + 2*q],   v.x, b0);
                    b1 = ffma2(w[10 + 2*q+1], v.y, b1);
                }
                float2 pr;
                pr.x = hsum2(a0) + hsum2(a1);
                pr.y = hsum2(b0) + hsum2(b1);
                *(float2*)&pout[row * NGR + gr0] = pr;
            }
        }

        // commit xg prefetch to other parity
        if (pi0 >= 0) ((float4*)&S.xb[s1 & 1][0][0])[pi0] = pf0;
        if (pi1 >= 0) ((float4*)&S.xb[s1 & 1][0][0])[pi1] = pf1;
        slot_bar(slot);

        // ===== PHASE B: combine + activations + h update (1120 tasks/slot) =====
        #pragma unroll
        for (int k = 0; k < 3; k++) {
            int t = r + SLOT_T * k;
            if (t < 2 * NR * HSZ) {
                int lay = t / (NR * HSZ);
                int rem = t - lay * (NR * HSZ);
                int row = rem / HSZ;
                int j   = rem - row * HSZ;
                if (lay == 0) {
                    if (s < TSZ) {
                        float hr = S.pA[0][row][j]        + S.pA[1][row][j];
                        float hz = S.pA[0][row][40 + j]   + S.pA[1][row][40 + j];
                        float hn = S.pA[0][row][80 + j]   + S.pA[1][row][80 + j];
                        const float* xv = S.xb[s & 1][row];
                        float r_ = sigm(xv[j]      + hr + C.bhh0[j]);
                        float z_ = sigm(xv[40 + j] + hz + C.bhh0[40 + j]);
                        float n_ = tanh_f(fmaf(r_, hn + C.bhh0[80 + j], xv[80 + j]));
                        float ho = S.h0[row][j];
                        S.h0[row][j] = fmaf(z_, ho - n_, n_);
                    }
                } else {
                    if (s >= 1) {
                        float ir = S.pB[0][0][row][j]      + S.pB[0][1][row][j];
                        float hr = S.pB[1][0][row][j]      + S.pB[1][1][row][j];
                        float iz = S.pB[0][0][row][40 + j] + S.pB[0][1][row][40 + j];
                        float hz = S.pB[1][0][row][40 + j] + S.pB[1][1][row][40 + j];
                        float in_ = S.pB[0][0][row][80 + j] + S.pB[0][1][row][80 + j];
                        float hn  = S.pB[1][0][row][80 + j] + S.pB[1][1][row][80 + j];
                        float r_ = sigm(ir + hr + C.bih1[j]      + C.bhh1[j]);
                        float z_ = sigm(iz + hz + C.bih1[40 + j] + C.bhh1[40 + j]);
                        float n_ = tanh_f(fmaf(r_, hn + C.bhh1[80 + j],
                                                   in_ + C.bih1[80 + j]));
                        float ho = S.h1[row][j];
                        S.h1[row][j] = fmaf(z_, ho - n_, n_);
                    }
                }
            }
        }
        slot_bar(slot);
    }

    // ---- write final layer-1 hidden state (clamped rows dup, benign) ----
    for (int e = r; e < NR * HSZ; e += SLOT_T) {
        int row = e / HSZ, jj = e % HSZ;
        int grow = base + row; if (grow > NB - 1) grow = NB - 1;
        out[grow * HSZ + jj] = S.h1[row][jj];
    }
}

extern "C" void kernel_launch(void* const* d_in, const int* in_sizes, int n_in,
                              void* d_out, int out_size) {
    const float* x    = (const float*)d_in[0];
    const float* Wih0 = (const float*)d_in[1];
    const float* Whh0 = (const float*)d_in[2];
    const float* bih0 = (const float*)d_in[3];
    const float* bhh0 = (const float*)d_in[4];
    const float* Wih1 = (const float*)d_in[5];
    const float* Whh1 = (const float*)d_in[6];
    const float* bih1 = (const float*)d_in[7];
    const float* bhh1 = (const float*)d_in[8];
    float* out = (float*)d_out;

    xg_prepass<<<NB, 128>>>(x, Wih0, bih0);

    const int smem_bytes = (int)sizeof(CTAS);
    cudaFuncSetAttribute(gru_main,
                         cudaFuncAttributeMaxDynamicSharedMemorySize, smem_bytes);
    gru_main<<<148, CTA_T, smem_bytes>>>(Whh0, bhh0, Wih1, Whh1, bih1, bhh1, out);
}